// round 17
// baseline (speedup 1.0000x reference)
#include <cuda_runtime.h>
#include <cuda_fp16.h>
#include <cstdint>
#include <math.h>

// CBTree B=4, L=9, d=256.
// 1-term fp16: A=hi(u) (K=512), B=hi(W) (K=512), 8 chunks of 64.
// l=7: fused GEMM (tanh+combine -> Anext).
// l=6,5,4: split-K GEMM with FUSED serial-ticket reduction epilogue
//          (last CTA per tile sums partials in fixed order + bias/tanh/combine).
// l=3..0: fp32 SIMT warp-per-output.

#define D 256
#define KA 1024          // Acat row stride in elements
#define ROWA 2048        // A row bytes
#define ROWBB 1024       // B row bytes (512 fp16)
#define NCH 8
#define SROW 144
#define TILE_B (128 * SROW)
#define STAGE (2 * TILE_B)            // 36864
#define NSTAGE 3
#define SMEM_TOTAL (NSTAGE * STAGE)   // 110592 (2 CTAs/SM)
#define HST 132
#define NTHR 512

// ---------------- static device scratch ----------------
__device__ __half g_Acat0[16384 * 1024];
__device__ __half g_Acat1[16384 * 1024];
__device__ __half g_Bcat[256 * 512];
__device__ float g_part[16384 * 256];
__device__ float g_hsA[256 * 256];
__device__ float g_hsB[256 * 256];
__device__ int g_cnt[128];

// ---------------- helpers ----------------
__device__ __forceinline__ uint32_t smem_u32(const void* p) {
    uint32_t a;
    asm("{ .reg .u64 t; cvta.to.shared.u64 t, %1; cvt.u32.u64 %0, t; }" : "=r"(a) : "l"(p));
    return a;
}
__device__ __forceinline__ void cp_async16(uint32_t dst, const void* src) {
    asm volatile("cp.async.cg.shared.global [%0], [%1], 16;" :: "r"(dst), "l"(src));
}
#define CP_COMMIT() asm volatile("cp.async.commit_group;" ::: "memory")

__device__ __forceinline__ void ldm_x4(uint32_t* r, uint32_t addr) {
    asm volatile("ldmatrix.sync.aligned.m8n8.x4.shared.b16 {%0,%1,%2,%3}, [%4];"
                 : "=r"(r[0]), "=r"(r[1]), "=r"(r[2]), "=r"(r[3]) : "r"(addr));
}
__device__ __forceinline__ void mma_f16(float* c, const uint32_t* a, uint32_t b0, uint32_t b1) {
    asm volatile("mma.sync.aligned.m16n8k16.row.col.f32.f16.f16.f32 "
                 "{%0,%1,%2,%3}, {%4,%5,%6,%7}, {%8,%9}, {%0,%1,%2,%3};"
                 : "+f"(c[0]), "+f"(c[1]), "+f"(c[2]), "+f"(c[3])
                 : "r"(a[0]), "r"(a[1]), "r"(a[2]), "r"(a[3]), "r"(b0), "r"(b1));
}

// Per-chunk compute for 32x32 warp tile: 4 ldm_x4 + 8 MMA per kk.
__device__ __forceinline__ void compute_chunk(uint32_t aAddr, uint32_t bAddr,
                                              float acc[2][4][4]) {
#pragma unroll
    for (int kk = 0; kk < 4; kk++) {
        uint32_t a0[4], a1[4], b0[4], b1[4];
        ldm_x4(a0, aAddr + kk * 32);
        ldm_x4(a1, aAddr + 16 * SROW + kk * 32);
        ldm_x4(b0, bAddr + kk * 32);
        ldm_x4(b1, bAddr + 16 * SROW + kk * 32);
        mma_f16(acc[0][0], a0, b0[0], b0[1]);
        mma_f16(acc[0][1], a0, b0[2], b0[3]);
        mma_f16(acc[0][2], a0, b1[0], b1[1]);
        mma_f16(acc[0][3], a0, b1[2], b1[3]);
        mma_f16(acc[1][0], a1, b0[0], b0[1]);
        mma_f16(acc[1][1], a1, b0[2], b0[3]);
        mma_f16(acc[1][2], a1, b1[0], b1[1]);
        mma_f16(acc[1][3], a1, b1[2], b1[3]);
    }
}

// ---------------- prep: Bcat = hi(W) fp16 + zero split-K counters ----------------
__global__ void prep_w_kernel(const float* __restrict__ Wl,
                              const float* __restrict__ Wr,
                              __half* __restrict__ Bcat) {
    int idx = blockIdx.x * blockDim.x + threadIdx.x;
    if (idx < 128) g_cnt[idx] = 0;
    if (idx >= D * 512) return;
    int n = idx >> 9;
    int k = idx & 511;
    float w = (k < D) ? Wl[n * D + k] : Wr[n * D + (k - D)];
    Bcat[(size_t)n * 512 + k] = __float2half_rn(w);
}

// ---------------- leaf reduce -> Acat hi halves (2 quads/thread, MLP=8) ----------------
__global__ void __launch_bounds__(256)
leaf_reduce_kernel(const float* __restrict__ h,
                   __half* __restrict__ Acat,
                   int n_par) {
    int idx = blockIdx.x * blockDim.x + threadIdx.x;   // n_par * 32
    if (idx >= n_par * 32) return;
    int p = idx >> 5;
    int q = idx & 31;                                  // quads q and q+32
    const float4* hp = (const float4*)(h + (size_t)p * 1024);
    float4 a0 = hp[q],       b0 = hp[64 + q],  c0 = hp[128 + q],  d0 = hp[192 + q];
    float4 a1 = hp[32 + q],  b1 = hp[96 + q],  c1 = hp[160 + q],  d1 = hp[224 + q];

    __half lh0[4], rh0[4], lh1[4], rh1[4];
    lh0[0] = __float2half_rn(a0.x + (2.f/3.f) * b0.x + (1.f/3.f) * c0.x);
    lh0[1] = __float2half_rn(a0.y + (2.f/3.f) * b0.y + (1.f/3.f) * c0.y);
    lh0[2] = __float2half_rn(a0.z + (2.f/3.f) * b0.z + (1.f/3.f) * c0.z);
    lh0[3] = __float2half_rn(a0.w + (2.f/3.f) * b0.w + (1.f/3.f) * c0.w);
    rh0[0] = __float2half_rn((1.f/3.f) * b0.x + (2.f/3.f) * c0.x + d0.x);
    rh0[1] = __float2half_rn((1.f/3.f) * b0.y + (2.f/3.f) * c0.y + d0.y);
    rh0[2] = __float2half_rn((1.f/3.f) * b0.z + (2.f/3.f) * c0.z + d0.z);
    rh0[3] = __float2half_rn((1.f/3.f) * b0.w + (2.f/3.f) * c0.w + d0.w);
    lh1[0] = __float2half_rn(a1.x + (2.f/3.f) * b1.x + (1.f/3.f) * c1.x);
    lh1[1] = __float2half_rn(a1.y + (2.f/3.f) * b1.y + (1.f/3.f) * c1.y);
    lh1[2] = __float2half_rn(a1.z + (2.f/3.f) * b1.z + (1.f/3.f) * c1.z);
    lh1[3] = __float2half_rn(a1.w + (2.f/3.f) * b1.w + (1.f/3.f) * c1.w);
    rh1[0] = __float2half_rn((1.f/3.f) * b1.x + (2.f/3.f) * c1.x + d1.x);
    rh1[1] = __float2half_rn((1.f/3.f) * b1.y + (2.f/3.f) * c1.y + d1.y);
    rh1[2] = __float2half_rn((1.f/3.f) * b1.z + (2.f/3.f) * c1.z + d1.z);
    rh1[3] = __float2half_rn((1.f/3.f) * b1.w + (2.f/3.f) * c1.w + d1.w);

    __half* arow = Acat + (size_t)p * KA;
    *(uint2*)(arow + q * 4)             = *(const uint2*)lh0;
    *(uint2*)(arow + 256 + q * 4)       = *(const uint2*)rh0;
    *(uint2*)(arow + 128 + q * 4)       = *(const uint2*)lh1;
    *(uint2*)(arow + 384 + q * 4)       = *(const uint2*)rh1;
}

// ======== stage loader (512 threads) ========
__device__ __forceinline__ void load_stage_g(uint32_t sbase, int slot, int it,
                                             const char* Ab, const char* Bb, int tid) {
    uint32_t sA = sbase + slot * STAGE;
    uint32_t sB = sA + TILE_B;
#pragma unroll
    for (int i = 0; i < 2; i++) {
        int id = i * NTHR + tid;
        int r = id >> 3, c = id & 7;
        cp_async16(sA + r * SROW + c * 16, Ab + (size_t)r * ROWA + it * 128 + c * 16);
    }
#pragma unroll
    for (int i = 0; i < 2; i++) {
        int id = i * NTHR + tid;
        int r = id >> 3, c = id & 7;
        cp_async16(sB + r * SROW + c * 16, Bb + (size_t)r * ROWBB + it * 128 + c * 16);
    }
    CP_COMMIT();
}

// ---------------- l=7: GEMM (8 chunks) + fused tanh/combine epilogue ----------------
__global__ void __launch_bounds__(NTHR, 2)
gemm_fused_l7(const __half* __restrict__ A,
              const __half* __restrict__ B,
              const float* __restrict__ bias,
              __half* __restrict__ Anext, int M) {
    extern __shared__ __align__(128) char smem[];
    const uint32_t sbase = smem_u32(smem);
    const int tid = threadIdx.x;
    const int wid = tid >> 5;
    const int lid = tid & 31;
    const int bn = blockIdx.x * 128;
    const int bm = blockIdx.y * 128;

    const char* Ab = (const char*)A + (size_t)bm * ROWA;
    const char* Bb = (const char*)B + (size_t)bn * ROWBB;

    float acc[2][4][4];
#pragma unroll
    for (int mf = 0; mf < 2; mf++)
#pragma unroll
        for (int nf = 0; nf < 4; nf++)
#pragma unroll
            for (int q = 0; q < 4; q++) acc[mf][nf][q] = 0.0f;

    const int wm = (wid & 3) * 32;
    const int wn = (wid >> 2) * 32;
    const uint32_t aOff = (uint32_t)(wm + (lid & 7) + ((lid & 8) ? 8 : 0)) * SROW +
                          ((lid & 16) ? 16 : 0);
    const uint32_t bOff = (uint32_t)(wn + (lid & 7) + ((lid & 16) ? 8 : 0)) * SROW +
                          ((lid & 8) ? 16 : 0);

    load_stage_g(sbase, 0, 0, Ab, Bb, tid);
    load_stage_g(sbase, 1, 1, Ab, Bb, tid);

    for (int it = 0; it < NCH; it++) {
        if (it + 2 < NCH) {
            asm volatile("cp.async.wait_group 1;" ::: "memory");
        } else {
            asm volatile("cp.async.wait_group 0;" ::: "memory");
        }
        __syncthreads();
        if (it + 2 < NCH)
            load_stage_g(sbase, (it + 2) % NSTAGE, it + 2, Ab, Bb, tid);

        uint32_t sA = sbase + (it % NSTAGE) * STAGE;
        compute_chunk(sA + aOff, sA + TILE_B + bOff, acc);
    }
    __syncthreads();

    // epilogue: tanh(acc+bias) -> smem h tile
    float* hs = (float*)smem;
#pragma unroll
    for (int mf = 0; mf < 2; mf++) {
#pragma unroll
        for (int half = 0; half < 2; half++) {
            int r = wm + mf * 16 + (lid >> 2) + half * 8;
            const float* brow = bias + (size_t)(bm + r) * D + bn + wn;
            float* hrow = hs + r * HST + wn;
#pragma unroll
            for (int nf = 0; nf < 4; nf++) {
                int col = nf * 8 + 2 * (lid & 3);
                float2 bv = *(const float2*)(brow + col);
                hrow[col] = tanhf(acc[mf][nf][half * 2 + 0] + bv.x);
                hrow[col + 1] = tanhf(acc[mf][nf][half * 2 + 1] + bv.y);
            }
        }
    }
    __syncthreads();

    // fused child-combine -> Anext hi columns [bn, bn+128)
    {
        int p = tid >> 4;
        int g = tid & 15;
        int pg = (bm >> 2) + p;
        const float* h0 = hs + (4 * p + 0) * HST;
        const float* h1 = hs + (4 * p + 1) * HST;
        const float* h2 = hs + (4 * p + 2) * HST;
        const float* h3 = hs + (4 * p + 3) * HST;
        __half* arow = Anext + (size_t)pg * KA;
        int c0 = g * 8;
        __half lh[8], rh[8];
#pragma unroll
        for (int j = 0; j < 8; j++) {
            float a = h0[c0 + j], b = h1[c0 + j], c = h2[c0 + j], d = h3[c0 + j];
            lh[j] = __float2half_rn(a + (2.f/3.f) * b + (1.f/3.f) * c);
            rh[j] = __float2half_rn((1.f/3.f) * b + (2.f/3.f) * c + d);
        }
        int cL = bn + c0;
        *(uint4*)(arow + cL) = *(const uint4*)lh;
        *(uint4*)(arow + 256 + cL) = *(const uint4*)rh;
    }
}

// ---------------- split-K GEMM + fused serial-ticket reduction (l=6,5,4) ----------------
// Last CTA per (bm,bn) tile sums S partials in fixed order, applies bias+tanh,
// then combine -> Anext (hi) or hout fp32, for its 128-column slice.
__global__ void __launch_bounds__(NTHR, 2)
gemm_partial_kernel(const __half* __restrict__ A,
                    const __half* __restrict__ B,
                    float* __restrict__ P,
                    const float* __restrict__ bias,
                    __half* __restrict__ Anext,
                    float* __restrict__ hout,
                    int M, int cnt, int S, int cntBase) {
    extern __shared__ __align__(128) char smem[];
    const uint32_t sbase = smem_u32(smem);
    const int tid = threadIdx.x;
    const int wid = tid >> 5;
    const int lid = tid & 31;
    const int bn = blockIdx.x * 128;
    const int bm = blockIdx.y * 128;
    const int c0 = blockIdx.z * cnt;

    const char* Ab = (const char*)A + (size_t)bm * ROWA;
    const char* Bb = (const char*)B + (size_t)bn * ROWBB;
    float* Pb = P + ((size_t)blockIdx.z * M + bm) * D + bn;

    float acc[2][4][4];
#pragma unroll
    for (int mf = 0; mf < 2; mf++)
#pragma unroll
        for (int nf = 0; nf < 4; nf++)
#pragma unroll
            for (int q = 0; q < 4; q++) acc[mf][nf][q] = 0.0f;

    const int wm = (wid & 3) * 32;
    const int wn = (wid >> 2) * 32;
    const uint32_t aOff = (uint32_t)(wm + (lid & 7) + ((lid & 8) ? 8 : 0)) * SROW +
                          ((lid & 16) ? 16 : 0);
    const uint32_t bOff = (uint32_t)(wn + (lid & 7) + ((lid & 16) ? 8 : 0)) * SROW +
                          ((lid & 8) ? 16 : 0);

    load_stage_g(sbase, 0, c0, Ab, Bb, tid);
    if (cnt > 1) load_stage_g(sbase, 1, c0 + 1, Ab, Bb, tid);

    for (int i = 0; i < cnt; i++) {
        if (i + 2 < cnt) {
            asm volatile("cp.async.wait_group 1;" ::: "memory");
        } else {
            asm volatile("cp.async.wait_group 0;" ::: "memory");
        }
        __syncthreads();
        if (i + 2 < cnt)
            load_stage_g(sbase, (i + 2) % NSTAGE, c0 + i + 2, Ab, Bb, tid);

        uint32_t sA = sbase + (i % NSTAGE) * STAGE;
        compute_chunk(sA + aOff, sA + TILE_B + bOff, acc);
    }

    // write fp32 partial tile
#pragma unroll
    for (int mf = 0; mf < 2; mf++) {
#pragma unroll
        for (int half = 0; half < 2; half++) {
            int r = wm + mf * 16 + (lid >> 2) + half * 8;
            float* prow = Pb + (size_t)r * D + wn;
#pragma unroll
            for (int nf = 0; nf < 4; nf++) {
                int col = nf * 8 + 2 * (lid & 3);
                float2 o;
                o.x = acc[mf][nf][half * 2 + 0];
                o.y = acc[mf][nf][half * 2 + 1];
                *(float2*)(prow + col) = o;
            }
        }
    }

    // ---- serial-ticket: last CTA of this tile does the reduction epilogue ----
    __shared__ int sLast;
    __threadfence();
    if (tid == 0) {
        int tileId = cntBase + blockIdx.y * gridDim.x + blockIdx.x;
        int old = atomicAdd(&g_cnt[tileId], 1);
        sLast = (old == S - 1) ? (tileId + 1) : 0;
    }
    __syncthreads();
    int lastId = sLast;
    if (!lastId) return;
    __threadfence();   // order partial reads after observing all arrivals

    // epilogue: p = tid>>4 (32 parents), g = tid&15 (8 cols each)
    {
        int p = tid >> 4;
        int g = tid & 15;
        int cc = g * 8;                    // local col within [0,128)
        float hv[4][8];
#pragma unroll
        for (int j = 0; j < 4; j++) {
            int row = bm + 4 * p + j;
            float sum[8];
            const float* p0 = P + (size_t)row * D + bn + cc;
#pragma unroll
            for (int x = 0; x < 8; x++) sum[x] = p0[x];
            for (int s = 1; s < S; s++) {
                const float* ps = P + ((size_t)s * M + row) * D + bn + cc;
#pragma unroll
                for (int x = 0; x < 8; x++) sum[x] += ps[x];
            }
            const float* brow = bias + (size_t)row * D + bn + cc;
#pragma unroll
            for (int x = 0; x < 8; x++) hv[j][x] = tanhf(sum[x] + brow[x]);
            if (hout) {
                float* orow = hout + (size_t)row * D + bn + cc;
#pragma unroll
                for (int x = 0; x < 8; x++) orow[x] = hv[j][x];
            }
        }
        if (Anext) {
            int pg = (bm >> 2) + p;
            __half lh[8], rh[8];
#pragma unroll
            for (int x = 0; x < 8; x++) {
                lh[x] = __float2half_rn(hv[0][x] + (2.f/3.f) * hv[1][x] + (1.f/3.f) * hv[2][x]);
                rh[x] = __float2half_rn((1.f/3.f) * hv[1][x] + (2.f/3.f) * hv[2][x] + hv[3][x]);
            }
            __half* arow = Anext + (size_t)pg * KA;
            *(uint4*)(arow + bn + cc) = *(const uint4*)lh;
            *(uint4*)(arow + 256 + bn + cc) = *(const uint4*)rh;
        }
    }
    __syncthreads();
    if (tid == 0) g_cnt[lastId - 1] = 0;   // reset for next graph replay
}

// ---------------- small levels (M<=64): fp32 warp-per-output ----------------
__global__ void __launch_bounds__(256)
small_level_kernel(const float* __restrict__ hprev,
                   const float* __restrict__ Wl,
                   const float* __restrict__ Wr,
                   const float* __restrict__ bias,
                   float* __restrict__ hout, int Mout) {
    int gw = (blockIdx.x * blockDim.x + threadIdx.x) >> 5;
    int lid = threadIdx.x & 31;
    if (gw >= Mout * D) return;
    int p = gw >> 8;
    int n = gw & 255;
    const float* h0 = hprev + (size_t)(4 * p) * D;
    const float* wl = Wl + (size_t)n * D;
    const float* wr = Wr + (size_t)n * D;
    float acc = 0.f;
#pragma unroll
    for (int i = 0; i < 8; i++) {
        int k = lid + i * 32;
        float a = h0[k], b = h0[D + k], c = h0[2 * D + k], d = h0[3 * D + k];
        float uL = a + (2.f/3.f) * b + (1.f/3.f) * c;
        float uR = (1.f/3.f) * b + (2.f/3.f) * c + d;
        acc = fmaf(uL, wl[k], acc);
        acc = fmaf(uR, wr[k], acc);
    }
#pragma unroll
    for (int o = 16; o; o >>= 1) acc += __shfl_xor_sync(0xffffffffu, acc, o);
    if (lid == 0)
        hout[(size_t)p * D + n] = tanhf(acc + bias[(size_t)p * D + n]);
}

// ---------------- launcher ----------------
extern "C" void kernel_launch(void* const* d_in, const int* in_sizes, int n_in,
                              void* d_out, int out_size) {
    const float* vectors = (const float*)d_in[0];
    const float* Wl = (const float*)d_in[1];
    const float* Wr = (const float*)d_in[2];
    float* out = (float*)d_out;

    __half *Acat0, *Acat1, *Bcat;
    float *part, *hsA, *hsB;
    cudaGetSymbolAddress((void**)&Acat0, g_Acat0);
    cudaGetSymbolAddress((void**)&Acat1, g_Acat1);
    cudaGetSymbolAddress((void**)&Bcat, g_Bcat);
    cudaGetSymbolAddress((void**)&part, g_part);
    cudaGetSymbolAddress((void**)&hsA, g_hsA);
    cudaGetSymbolAddress((void**)&hsB, g_hsB);

    cudaFuncSetAttribute(gemm_fused_l7,
                         cudaFuncAttributeMaxDynamicSharedMemorySize, SMEM_TOTAL);
    cudaFuncSetAttribute(gemm_fused_l7,
                         cudaFuncAttributePreferredSharedMemoryCarveout, 100);
    cudaFuncSetAttribute(gemm_partial_kernel,
                         cudaFuncAttributeMaxDynamicSharedMemorySize, SMEM_TOTAL);
    cudaFuncSetAttribute(gemm_partial_kernel,
                         cudaFuncAttributePreferredSharedMemoryCarveout, 100);

    prep_w_kernel<<<(D * 512 + 255) / 256, 256>>>(Wl, Wr, Bcat);

    static const int offs[9] = {0, 1, 5, 21, 85, 341, 1365, 5461, 21845};

    const float* leaves = vectors + (size_t)offs[8] * D;
    leaf_reduce_kernel<<<(16384 * 32 + 255) / 256, 256>>>(leaves, Acat0, 16384);

    // l=7: fused GEMM, Acat0 -> Acat1
    {
        dim3 grid(2, 128);
        gemm_fused_l7<<<grid, NTHR, SMEM_TOTAL>>>(
            Acat0, Bcat, vectors + (size_t)offs[7] * D, Acat1, 16384);
    }

    // l=6: split-K S=4 cnt=2, fused reduction, Acat1 -> Acat0  (tiles 2x32=64, base 0)
    {
        dim3 grid(2, 32, 4);
        gemm_partial_kernel<<<grid, NTHR, SMEM_TOTAL>>>(
            Acat1, Bcat, part, vectors + (size_t)offs[6] * D, Acat0, nullptr,
            4096, 2, 4, 0);
    }

    // l=5: split-K S=8 cnt=1, Acat0 -> Acat1  (tiles 2x8=16, base 64)
    {
        dim3 grid(2, 8, 8);
        gemm_partial_kernel<<<grid, NTHR, SMEM_TOTAL>>>(
            Acat0, Bcat, part, vectors + (size_t)offs[5] * D, Acat1, nullptr,
            1024, 1, 8, 64);
    }

    // l=4: split-K S=8 cnt=1, Acat1 -> fp32 h (hsA)  (tiles 2x2=4, base 80)
    {
        dim3 grid(2, 2, 8);
        gemm_partial_kernel<<<grid, NTHR, SMEM_TOTAL>>>(
            Acat1, Bcat, part, vectors + (size_t)offs[4] * D, nullptr, hsA,
            256, 1, 8, 80);
    }

    // l=3..0: fp32 SIMT. hsA -> hsB -> hsA -> hsB -> out
    const float* hin = hsA;
    for (int l = 3; l >= 0; --l) {
        int M = 1 << (2 * l);
        float* hout = (l == 0) ? out : ((l & 1) ? hsB : hsA);
        const float* bias = vectors + (size_t)offs[l] * D;
        int nwarps = M * D;
        small_level_kernel<<<(nwarps * 32 + 255) / 256, 256>>>(hin, Wl, Wr, bias, hout, M);
        hin = hout;
    }
}